// round 6
// baseline (speedup 1.0000x reference)
#include <cuda_runtime.h>
#include <cstdint>

#define NPTS 200000
#define DIM  128
#define KC   512
#define BN   128
#define BK   128
#define NT   (KC / BK)

// Scratch (allocation-free rule: __device__ globals)
__device__ float g_sums[KC * DIM];
__device__ float g_counts[KC];
__device__ float g_c2[KC];

typedef unsigned long long ull;

__device__ __forceinline__ void fma2(ull& c, ull a, ull b) {
    asm("fma.rn.f32x2 %0, %1, %2, %0;" : "+l"(c) : "l"(a), "l"(b));
}
__device__ __forceinline__ void unpack2(float& lo, float& hi, ull v) {
    asm("mov.b64 {%0, %1}, %2;" : "=f"(lo), "=f"(hi) : "l"(v));
}

// Zero scratch + precompute ||c||^2 per center.
__global__ void prep_kernel(const float* __restrict__ centers) {
    int i = blockIdx.x * blockDim.x + threadIdx.x;
    if (i < KC * DIM) g_sums[i] = 0.0f;
    if (i < KC) {
        g_counts[i] = 0.0f;
        const float* c = centers + (size_t)i * DIM;
        float s = 0.0f;
        #pragma unroll 8
        for (int d = 0; d < DIM; d++) s = fmaf(c[d], c[d], s);
        g_c2[i] = s;
    }
}

// Fused: distances (f32x2 GEMM) -> argmin -> assign write -> segment-sum reductions.
__global__ __launch_bounds__(256, 1)
void assign_kernel(const float* __restrict__ F, const float* __restrict__ centers,
                   float* __restrict__ assign_out) {
    extern __shared__ float smem[];
    float*  Fs = smem;                            // [DIM][BN]    64 KB (transposed)
    float2* Cs = (float2*)(smem + DIM * BN);      // [DIM][BK]   128 KB (transposed, duplicated)
    int* s_assign = (int*)(Cs + (size_t)DIM * BK);// [BN]

    const int tid  = threadIdx.x;
    const int tx   = tid & 15;   // center-octet lane
    const int ty   = tid >> 4;   // point-octet lane
    const int pt_l = tid >> 1;   // 0..127 (loader mapping)
    const int half = tid & 1;    // D half
    const long long gp0 = (long long)blockIdx.x * BN;

    // ---- Load F tile, transposed into smem (2-way STS conflicts only) ----
    {
        long long gp = gp0 + pt_l;
        const float4* frow = (const float4*)(F + gp * DIM);
        #pragma unroll
        for (int i = 0; i < 16; i++) {
            int d0 = half * 64 + i * 4;
            float4 v = make_float4(0.f, 0.f, 0.f, 0.f);
            if (gp < NPTS) v = frow[d0 >> 2];
            Fs[(d0 + 0) * BN + pt_l] = v.x;
            Fs[(d0 + 1) * BN + pt_l] = v.y;
            Fs[(d0 + 2) * BN + pt_l] = v.z;
            Fs[(d0 + 3) * BN + pt_l] = v.w;
        }
    }

    float minv[8];
    int   mini[8];
    #pragma unroll
    for (int q = 0; q < 8; q++) { minv[q] = 3.4e38f; mini[q] = 0; }

    const float*  fsp = Fs + ty * 8;
    const float2* csp = Cs + tx * 8;

    for (int ct = 0; ct < NT; ct++) {
        __syncthreads();   // previous tile's compute done before overwriting Cs
        // ---- Load center tile, transposed + pre-duplicated (float2 (v,v)) ----
        {
            int gc = ct * BK + pt_l;
            const float4* crow = (const float4*)(centers + (size_t)gc * DIM);
            #pragma unroll
            for (int i = 0; i < 16; i++) {
                int d0 = half * 64 + i * 4;
                float4 v = crow[d0 >> 2];
                Cs[(d0 + 0) * BK + pt_l] = make_float2(v.x, v.x);
                Cs[(d0 + 1) * BK + pt_l] = make_float2(v.y, v.y);
                Cs[(d0 + 2) * BK + pt_l] = make_float2(v.z, v.z);
                Cs[(d0 + 3) * BK + pt_l] = make_float2(v.w, v.w);
            }
        }
        float c2r[8];
        #pragma unroll
        for (int j = 0; j < 8; j++) c2r[j] = g_c2[ct * BK + tx * 8 + j];
        __syncthreads();

        ull acc[4][8];
        #pragma unroll
        for (int i = 0; i < 4; i++)
            #pragma unroll
            for (int j = 0; j < 8; j++) acc[i][j] = 0ULL;

        // ---- Mainloop: 32 FMA2 + 6 LDS.128 per d ----
        #pragma unroll 2
        for (int d = 0; d < DIM; d++) {
            ulonglong2 fa = *(const ulonglong2*)(fsp + d * BN);      // pts 0..3 (2 pairs)
            ulonglong2 fb = *(const ulonglong2*)(fsp + d * BN + 4);  // pts 4..7
            const ulonglong2* cp = (const ulonglong2*)(csp + d * BK);
            ulonglong2 ca = cp[0], cb = cp[1], cc = cp[2], cd = cp[3];
            ull f[4] = {fa.x, fa.y, fb.x, fb.y};
            ull c[8] = {ca.x, ca.y, cb.x, cb.y, cc.x, cc.y, cd.x, cd.y};
            #pragma unroll
            for (int i = 0; i < 4; i++)
                #pragma unroll
                for (int j = 0; j < 8; j++) fma2(acc[i][j], f[i], c[j]);
        }

        // ---- Score: c2 - 2*dot ; running argmin (ascending center idx -> first-tie kept) ----
        #pragma unroll
        for (int j = 0; j < 8; j++) {
            int   cg  = ct * BK + tx * 8 + j;
            float c2v = c2r[j];
            #pragma unroll
            for (int i = 0; i < 4; i++) {
                float lo, hi;
                unpack2(lo, hi, acc[i][j]);
                float s0 = fmaf(-2.0f, lo, c2v);
                float s1 = fmaf(-2.0f, hi, c2v);
                if (s0 < minv[2*i])     { minv[2*i]     = s0; mini[2*i]     = cg; }
                if (s1 < minv[2*i + 1]) { minv[2*i + 1] = s1; mini[2*i + 1] = cg; }
            }
        }
    }

    // ---- Reduce argmin across the 16 tx lanes (index tiebreak = jnp first-index) ----
    #pragma unroll
    for (int m = 1; m < 16; m <<= 1) {
        #pragma unroll
        for (int q = 0; q < 8; q++) {
            float ov = __shfl_xor_sync(0xffffffffu, minv[q], m);
            int   oi = __shfl_xor_sync(0xffffffffu, mini[q], m);
            if (ov < minv[q] || (ov == minv[q] && oi < mini[q])) { minv[q] = ov; mini[q] = oi; }
        }
    }

    if (tx == 0) {
        #pragma unroll
        for (int q = 0; q < 8; q++) {
            int pl = ty * 8 + q;
            s_assign[pl] = mini[q];
            long long gp = gp0 + pl;
            if (assign_out != nullptr && gp < NPTS) assign_out[gp] = (float)mini[q];
        }
    }
    __syncthreads();

    // ---- Segment sums: vectorized global reductions (fire-and-forget) ----
    {
        long long gp = gp0 + pt_l;
        if (gp < NPTS) {
            int k = s_assign[pt_l];
            float* dst = g_sums + (size_t)k * DIM;
            #pragma unroll
            for (int i = 0; i < 16; i++) {
                int d0 = half * 64 + i * 4;
                float a = Fs[(d0 + 0) * BN + pt_l];
                float b = Fs[(d0 + 1) * BN + pt_l];
                float c = Fs[(d0 + 2) * BN + pt_l];
                float e = Fs[(d0 + 3) * BN + pt_l];
                asm volatile("red.global.add.v4.f32 [%0], {%1,%2,%3,%4};"
                             :: "l"(dst + d0), "f"(a), "f"(b), "f"(c), "f"(e) : "memory");
            }
            if (half == 0) {
                asm volatile("red.global.add.f32 [%0], %1;"
                             :: "l"(g_counts + k), "f"(1.0f) : "memory");
            }
        }
    }
}

// new_centers = sums / max(counts, 1)
__global__ void finalize_kernel(float* __restrict__ out) {
    int i = blockIdx.x * blockDim.x + threadIdx.x;
    if (i < KC * DIM) {
        int k = i >> 7;
        out[i] = g_sums[i] / fmaxf(g_counts[k], 1.0f);
    }
}

extern "C" void kernel_launch(void* const* d_in, const int* in_sizes, int n_in,
                              void* d_out, int out_size) {
    const float* F       = (const float*)d_in[0];
    const float* centers = (const float*)d_in[1];
    float* out = (float*)d_out;
    // Output layout: new_centers [K*D] then assign [N] (cast to float).
    float* assign_out = (out_size >= KC * DIM + NPTS) ? (out + KC * DIM) : nullptr;

    size_t smem_bytes = (size_t)DIM * BN * sizeof(float)
                      + (size_t)DIM * BK * sizeof(float2)
                      + BN * sizeof(int);
    cudaFuncSetAttribute(assign_kernel, cudaFuncAttributeMaxDynamicSharedMemorySize,
                         (int)smem_bytes);

    prep_kernel<<<(KC * DIM + 255) / 256, 256>>>(centers);
    assign_kernel<<<(NPTS + BN - 1) / BN, 256, smem_bytes>>>(F, centers, assign_out);
    finalize_kernel<<<(KC * DIM + 255) / 256, 256>>>(out);
}

// round 7
// speedup vs baseline: 2.6012x; 2.6012x over previous
#include <cuda_runtime.h>
#include <cstdint>

#define NPTS 200000
#define DIM  128
#define KC   512
#define BN   128
#define BK   128
#define NT   (KC / BK)

// Scratch (allocation-free rule: __device__ globals)
__device__ float g_sums[KC * DIM];
__device__ float g_counts[KC];
__device__ float g_c2[KC];

typedef unsigned long long ull;

__device__ __forceinline__ void fma2(ull& c, ull a, ull b) {
    asm("fma.rn.f32x2 %0, %1, %2, %0;" : "+l"(c) : "l"(a), "l"(b));
}
__device__ __forceinline__ void unpack2(float& lo, float& hi, ull v) {
    asm("mov.b64 {%0, %1}, %2;" : "=f"(lo), "=f"(hi) : "l"(v));
}
__device__ __forceinline__ ull dup2(float c) {
    ull r;
    asm("mov.b64 %0, {%1, %1};" : "=l"(r) : "f"(c));
    return r;
}

// Zero scratch + precompute ||c||^2 (one warp per center).
__global__ void prep_kernel(const float* __restrict__ centers) {
    const int tid  = threadIdx.x;
    const int lane = tid & 31;
    // zero g_sums: 64 blocks x 256 threads x float4 = 65536 floats
    int zi = (blockIdx.x * blockDim.x + tid) * 4;
    if (zi < KC * DIM) *(float4*)(g_sums + zi) = make_float4(0.f, 0.f, 0.f, 0.f);
    int gi = blockIdx.x * blockDim.x + tid;
    if (gi < KC) g_counts[gi] = 0.0f;
    // c2: warp per center (8 warps/block, 64 blocks = 512 centers)
    int c = blockIdx.x * 8 + (tid >> 5);
    if (c < KC) {
        float4 v = ((const float4*)(centers + (size_t)c * DIM))[lane];
        float s = v.x * v.x + v.y * v.y + v.z * v.z + v.w * v.w;
        #pragma unroll
        for (int m = 16; m > 0; m >>= 1) s += __shfl_xor_sync(0xffffffffu, s, m);
        if (lane == 0) g_c2[c] = s;
    }
}

// Fused: distances (f32x2 GEMM) -> argmin -> assign write -> segment-sum reductions.
// Thread tile: 8 points (4 f32x2 pairs) x 8 centers (strided, conflict-free LDS).
__global__ __launch_bounds__(256, 1)
void assign_kernel(const float* __restrict__ F, const float* __restrict__ centers,
                   float* __restrict__ assign_out) {
    extern __shared__ float smem[];
    float* Fs = smem;                       // [DIM][BN]  64 KB, transposed, plain fp32
    float* Cs = smem + DIM * BN;            // [DIM][BK]  64 KB, transposed, plain fp32
    int* s_assign = (int*)(Cs + DIM * BK);  // [BN]

    const int tid  = threadIdx.x;
    const int tx   = tid & 15;   // center-lane
    const int ty   = tid >> 4;   // point-octet lane
    const int pt_l = tid >> 1;   // 0..127 (loader mapping)
    const int half = tid & 1;    // D half
    const long long gp0 = (long long)blockIdx.x * BN;

    // ---- Load F tile, transposed into smem ----
    {
        long long gp = gp0 + pt_l;
        const float4* frow = (const float4*)(F + gp * DIM);
        #pragma unroll
        for (int i = 0; i < 16; i++) {
            int d0 = half * 64 + i * 4;
            float4 v = make_float4(0.f, 0.f, 0.f, 0.f);
            if (gp < NPTS) v = frow[d0 >> 2];
            Fs[(d0 + 0) * BN + pt_l] = v.x;
            Fs[(d0 + 1) * BN + pt_l] = v.y;
            Fs[(d0 + 2) * BN + pt_l] = v.z;
            Fs[(d0 + 3) * BN + pt_l] = v.w;
        }
    }

    float minv[8];
    int   mini[8];
    #pragma unroll
    for (int q = 0; q < 8; q++) { minv[q] = 3.4e38f; mini[q] = 0; }

    const float* fsp = Fs + ty * 8;
    // Thread's centers (local idx): {4*tx .. 4*tx+3} and {4*(tx+16) .. 4*(tx+16)+3}
    const int cl0 = 4 * tx;
    const int cl1 = 4 * (tx + 16);

    for (int ct = 0; ct < NT; ct++) {
        __syncthreads();   // previous tile's compute done before overwriting Cs
        // ---- Load center tile, transposed, plain fp32 ----
        {
            int gc = ct * BK + pt_l;
            const float4* crow = (const float4*)(centers + (size_t)gc * DIM);
            #pragma unroll
            for (int i = 0; i < 16; i++) {
                int d0 = half * 64 + i * 4;
                float4 v = crow[d0 >> 2];
                Cs[(d0 + 0) * BK + pt_l] = v.x;
                Cs[(d0 + 1) * BK + pt_l] = v.y;
                Cs[(d0 + 2) * BK + pt_l] = v.z;
                Cs[(d0 + 3) * BK + pt_l] = v.w;
            }
        }
        float c2r[8];
        #pragma unroll
        for (int j = 0; j < 8; j++) {
            int cl = (j < 4) ? (cl0 + j) : (cl1 + (j - 4));
            c2r[j] = g_c2[ct * BK + cl];
        }
        __syncthreads();

        ull acc[4][8];
        #pragma unroll
        for (int i = 0; i < 4; i++)
            #pragma unroll
            for (int j = 0; j < 8; j++) acc[i][j] = 0ULL;

        // ---- Mainloop: 32 FMA2 + 4 conflict-free LDS.128 + 8 dup-movs per d ----
        #pragma unroll 2
        for (int d = 0; d < DIM; d++) {
            // F: 8 points as 4 fp32x2 pairs (broadcast across tx lanes)
            ulonglong2 fa = *(const ulonglong2*)(fsp + d * BN);      // pts 0..3
            ulonglong2 fb = *(const ulonglong2*)(fsp + d * BN + 4);  // pts 4..7
            // C: 8 centers, strided sets -> phase lanes read consecutive 16B units
            float4 ca = *(const float4*)(Cs + d * BK + cl0);
            float4 cb = *(const float4*)(Cs + d * BK + cl1);
            ull f[4] = {fa.x, fa.y, fb.x, fb.y};
            ull c[8];
            c[0] = dup2(ca.x); c[1] = dup2(ca.y); c[2] = dup2(ca.z); c[3] = dup2(ca.w);
            c[4] = dup2(cb.x); c[5] = dup2(cb.y); c[6] = dup2(cb.z); c[7] = dup2(cb.w);
            #pragma unroll
            for (int i = 0; i < 4; i++)
                #pragma unroll
                for (int j = 0; j < 8; j++) fma2(acc[i][j], f[i], c[j]);
        }

        // ---- Score: c2 - 2*dot ; running argmin (ascending idx within thread) ----
        #pragma unroll
        for (int j = 0; j < 8; j++) {
            int   cl  = (j < 4) ? (cl0 + j) : (cl1 + (j - 4));
            int   cg  = ct * BK + cl;
            float c2v = c2r[j];
            #pragma unroll
            for (int i = 0; i < 4; i++) {
                float lo, hi;
                unpack2(lo, hi, acc[i][j]);
                float s0 = fmaf(-2.0f, lo, c2v);
                float s1 = fmaf(-2.0f, hi, c2v);
                if (s0 < minv[2*i])     { minv[2*i]     = s0; mini[2*i]     = cg; }
                if (s1 < minv[2*i + 1]) { minv[2*i + 1] = s1; mini[2*i + 1] = cg; }
            }
        }
    }

    // ---- Reduce argmin across the 16 tx lanes (index tiebreak = first-index) ----
    #pragma unroll
    for (int m = 1; m < 16; m <<= 1) {
        #pragma unroll
        for (int q = 0; q < 8; q++) {
            float ov = __shfl_xor_sync(0xffffffffu, minv[q], m);
            int   oi = __shfl_xor_sync(0xffffffffu, mini[q], m);
            if (ov < minv[q] || (ov == minv[q] && oi < mini[q])) { minv[q] = ov; mini[q] = oi; }
        }
    }

    if (tx == 0) {
        #pragma unroll
        for (int q = 0; q < 8; q++) {
            int pl = ty * 8 + q;
            s_assign[pl] = mini[q];
            long long gp = gp0 + pl;
            if (assign_out != nullptr && gp < NPTS) assign_out[gp] = (float)mini[q];
        }
    }
    __syncthreads();

    // ---- Segment sums: vectorized global reductions (fire-and-forget) ----
    {
        long long gp = gp0 + pt_l;
        if (gp < NPTS) {
            int k = s_assign[pt_l];
            float* dst = g_sums + (size_t)k * DIM;
            #pragma unroll
            for (int i = 0; i < 16; i++) {
                int d0 = half * 64 + i * 4;
                float a = Fs[(d0 + 0) * BN + pt_l];
                float b = Fs[(d0 + 1) * BN + pt_l];
                float c = Fs[(d0 + 2) * BN + pt_l];
                float e = Fs[(d0 + 3) * BN + pt_l];
                asm volatile("red.global.add.v4.f32 [%0], {%1,%2,%3,%4};"
                             :: "l"(dst + d0), "f"(a), "f"(b), "f"(c), "f"(e) : "memory");
            }
            if (half == 0) {
                asm volatile("red.global.add.f32 [%0], %1;"
                             :: "l"(g_counts + k), "f"(1.0f) : "memory");
            }
        }
    }
}

// new_centers = sums / max(counts, 1)
__global__ void finalize_kernel(float* __restrict__ out) {
    int i = blockIdx.x * blockDim.x + threadIdx.x;
    if (i < KC * DIM) {
        int k = i >> 7;
        out[i] = g_sums[i] / fmaxf(g_counts[k], 1.0f);
    }
}

extern "C" void kernel_launch(void* const* d_in, const int* in_sizes, int n_in,
                              void* d_out, int out_size) {
    const float* F       = (const float*)d_in[0];
    const float* centers = (const float*)d_in[1];
    float* out = (float*)d_out;
    // Output layout: new_centers [K*D] then assign [N] (cast to float).
    float* assign_out = (out_size >= KC * DIM + NPTS) ? (out + KC * DIM) : nullptr;

    size_t smem_bytes = (size_t)DIM * BN * sizeof(float)
                      + (size_t)DIM * BK * sizeof(float)
                      + BN * sizeof(int);
    cudaFuncSetAttribute(assign_kernel, cudaFuncAttributeMaxDynamicSharedMemorySize,
                         (int)smem_bytes);

    prep_kernel<<<64, 256>>>(centers);
    assign_kernel<<<(NPTS + BN - 1) / BN, 256, smem_bytes>>>(F, centers, assign_out);
    finalize_kernel<<<(KC * DIM + 255) / 256, 256>>>(out);
}

// round 9
// speedup vs baseline: 3.3571x; 1.2906x over previous
#include <cuda_runtime.h>
#include <cuda_bf16.h>
#include <cstdint>

#define NPTS 200000
#define DIM  128
#define KC   512
#define BN   128
#define CHN  64
#define NCH  (KC / CHN)

// ---------------- device scratch (allocation-free rule) ----------------
__device__ float g_sums[KC * DIM];
__device__ float g_counts[KC];
__device__ float g_c2[KC];
__device__ __nv_bfloat16 g_bh[KC * DIM];
__device__ __nv_bfloat16 g_bm[KC * DIM];
__device__ __nv_bfloat16 g_bl[KC * DIM];

// ---------------- SMEM layout ----------------
// Rows padded to 272B: 8 consecutive rows hit 16B-units at banks 4i..4i+3
// (272/4 = 68 = 4 mod 32) -> conflict-free ldmatrix, no swizzle needed.
#define RS    272
#define A_SPL (128 * RS)          // 34816 per split
#define B_SPL (64 * RS)           // 17408 per split
#define B_BUF (3 * B_SPL)         // 52224 per buffer
#define OFF_ASSIGN 0              // 128 ints
#define OFF_C2     1024           // 512 floats
#define OFF_A      4096
#define OFF_B      (OFF_A + 3 * A_SPL)     // 108544
#define SMEM_TOTAL (OFF_B + 2 * B_BUF)     // 212992

__device__ __forceinline__ uint32_t smem_u32(const void* p) {
    uint32_t a;
    asm("{ .reg .u64 t; cvta.to.shared.u64 t, %1; cvt.u32.u64 %0, t; }" : "=r"(a) : "l"(p));
    return a;
}
__device__ __forceinline__ void ldsm4(uint32_t* r, uint32_t addr) {
    asm volatile("ldmatrix.sync.aligned.m8n8.x4.shared.b16 {%0,%1,%2,%3}, [%4];"
                 : "=r"(r[0]), "=r"(r[1]), "=r"(r[2]), "=r"(r[3]) : "r"(addr));
}
__device__ __forceinline__ void mma_bf16(float* c, const uint32_t* a, uint32_t b0, uint32_t b1) {
    asm volatile(
        "mma.sync.aligned.m16n8k16.row.col.f32.bf16.bf16.f32 "
        "{%0,%1,%2,%3}, {%4,%5,%6,%7}, {%8,%9}, {%0,%1,%2,%3};"
        : "+f"(c[0]), "+f"(c[1]), "+f"(c[2]), "+f"(c[3])
        : "r"(a[0]), "r"(a[1]), "r"(a[2]), "r"(a[3]), "r"(b0), "r"(b1));
}
__device__ __forceinline__ void cp_async16(uint32_t dst, const void* src) {
    uint64_t g;
    asm("cvta.to.global.u64 %0, %1;" : "=l"(g) : "l"(src));
    asm volatile("cp.async.cg.shared.global [%0], [%1], 16;" :: "r"(dst), "l"(g) : "memory");
}
#define CP_COMMIT() asm volatile("cp.async.commit_group;" ::: "memory")
#define CP_WAIT1()  asm volatile("cp.async.wait_group 1;" ::: "memory")
#define CP_WAIT0()  asm volatile("cp.async.wait_group 0;" ::: "memory")

__device__ __forceinline__ uint32_t pack2(__nv_bfloat16 a, __nv_bfloat16 b) {
    return (uint32_t)__bfloat16_as_ushort(a) | ((uint32_t)__bfloat16_as_ushort(b) << 16);
}

// ---------------- prep: zero scratch, c2, 3-way bf16 split of centers ----------------
__global__ void prep_kernel(const float* __restrict__ centers) {
    const int tid = threadIdx.x;
    const int t = blockIdx.x * 256 + tid;          // 0..16383
    *(float4*)(g_sums + t * 4) = make_float4(0.f, 0.f, 0.f, 0.f);
    if (t < KC) g_counts[t] = 0.0f;
    float4 v4 = *(const float4*)(centers + t * 4);
    float vv[4] = {v4.x, v4.y, v4.z, v4.w};
    #pragma unroll
    for (int e = 0; e < 4; e++) {
        float v = vv[e];
        __nv_bfloat16 h = __float2bfloat16(v);
        float r1 = v - __bfloat162float(h);
        __nv_bfloat16 m = __float2bfloat16(r1);
        float r2 = r1 - __bfloat162float(m);
        __nv_bfloat16 l = __float2bfloat16(r2);
        g_bh[t * 4 + e] = h;
        g_bm[t * 4 + e] = m;
        g_bl[t * 4 + e] = l;
    }
    int c = blockIdx.x * 8 + (tid >> 5);
    int lane = tid & 31;
    float4 cv = ((const float4*)(centers + (size_t)c * DIM))[lane];
    float s = cv.x * cv.x + cv.y * cv.y + cv.z * cv.z + cv.w * cv.w;
    #pragma unroll
    for (int mth = 16; mth > 0; mth >>= 1) s += __shfl_xor_sync(0xffffffffu, s, mth);
    if (lane == 0) g_c2[c] = s;
}

// ---------------- B chunk loader: 3 splits x 64 rows via cp.async ----------------
__device__ __forceinline__ void load_chunk(char* smem, uint32_t sb, int chunk, int buf, int tid) {
    const __nv_bfloat16* gsrc[3] = {g_bh, g_bm, g_bl};
    #pragma unroll
    for (int i = 0; i < 12; i++) {
        int u = i * 256 + tid;            // 0..3071
        int split = u >> 10;
        int r = (u >> 4) & 63;
        int q = u & 15;
        const __nv_bfloat16* src = gsrc[split] + ((size_t)(chunk * CHN + r)) * DIM + q * 8;
        uint32_t dst = sb + OFF_B + buf * B_BUF + split * B_SPL + r * RS + q * 16;
        cp_async16(dst, src);
    }
}

// ---------------- main fused kernel ----------------
__global__ __launch_bounds__(256, 1)
void assign_kernel(const float* __restrict__ F, float* __restrict__ assign_out) {
    extern __shared__ char smem[];
    const uint32_t sb = smem_u32(smem);
    const int tid  = threadIdx.x;
    const int wid  = tid >> 5;
    const int lane = tid & 31;
    const long long gp0 = (long long)blockIdx.x * BN;

    // c2 -> smem
    for (int i = tid; i < KC; i += 256) ((float*)(smem + OFF_C2))[i] = g_c2[i];

    // ---- Load + split A (F tile 128x128) ----
    {
        int row = tid >> 1, half = tid & 1;
        long long gp = gp0 + row;
        const float4* fr = (const float4*)(F + gp * DIM) + half * 16;
        #pragma unroll
        for (int g = 0; g < 8; g++) {
            float4 a = make_float4(0.f, 0.f, 0.f, 0.f), b = a;
            if (gp < NPTS) { a = fr[g * 2]; b = fr[g * 2 + 1]; }
            float v[8] = {a.x, a.y, a.z, a.w, b.x, b.y, b.z, b.w};
            __nv_bfloat16 h[8], m[8], l[8];
            #pragma unroll
            for (int e = 0; e < 8; e++) {
                h[e] = __float2bfloat16(v[e]);
                float r1 = v[e] - __bfloat162float(h[e]);
                m[e] = __float2bfloat16(r1);
                float r2 = r1 - __bfloat162float(m[e]);
                l[e] = __float2bfloat16(r2);
            }
            uint32_t doff = OFF_A + row * RS + (half * 64 + g * 8) * 2;
            *(uint4*)(smem + doff)             = make_uint4(pack2(h[0],h[1]), pack2(h[2],h[3]), pack2(h[4],h[5]), pack2(h[6],h[7]));
            *(uint4*)(smem + doff + A_SPL)     = make_uint4(pack2(m[0],m[1]), pack2(m[2],m[3]), pack2(m[4],m[5]), pack2(m[6],m[7]));
            *(uint4*)(smem + doff + 2 * A_SPL) = make_uint4(pack2(l[0],l[1]), pack2(l[2],l[3]), pack2(l[4],l[5]), pack2(l[6],l[7]));
        }
    }

    // prefetch chunk 0
    load_chunk(smem, sb, 0, 0, tid);
    CP_COMMIT();

    // per-lane fragment offsets (ldmatrix lane-address pattern)
    const int m0 = wid * 16;
    const int frow = (lane & 7) + ((lane >> 3) & 1) * 8;
    const int kblk = (lane >> 4) * 8;
    const uint32_t aoff = sb + OFF_A + (uint32_t)((m0 + frow) * RS + kblk * 2);
    const uint32_t boff = sb + OFF_B + (uint32_t)(frow * RS + kblk * 2);

    float mv[2] = {3.4e38f, 3.4e38f};
    int   mi[2] = {0, 0};

    #pragma unroll 1
    for (int c = 0; c < NCH; c++) {
        const int buf = c & 1;
        if (c + 1 < NCH) { load_chunk(smem, sb, c + 1, buf ^ 1, tid); CP_COMMIT(); CP_WAIT1(); }
        else             { CP_WAIT0(); }
        __syncthreads();

        float acc[8][4];
        #pragma unroll
        for (int nt = 0; nt < 8; nt++)
            #pragma unroll
            for (int r = 0; r < 4; r++) acc[nt][r] = 0.0f;

        const uint32_t bb = boff + buf * B_BUF;
        #pragma unroll
        for (int ks = 0; ks < 8; ks++) {
            uint32_t av[3][4];
            #pragma unroll
            for (int s = 0; s < 3; s++) ldsm4(av[s], aoff + s * A_SPL + ks * 32);
            #pragma unroll
            for (int ntp = 0; ntp < 4; ntp++) {
                uint32_t bv[3][4];
                #pragma unroll
                for (int s = 0; s < 3; s++)
                    ldsm4(bv[s], bb + s * B_SPL + ntp * (16 * RS) + ks * 32);
                float* aL = acc[2 * ntp];
                float* aH = acc[2 * ntp + 1];
                // hh, hm, mh, hl, lh, mm
                mma_bf16(aL, av[0], bv[0][0], bv[0][2]); mma_bf16(aH, av[0], bv[0][1], bv[0][3]);
                mma_bf16(aL, av[0], bv[1][0], bv[1][2]); mma_bf16(aH, av[0], bv[1][1], bv[1][3]);
                mma_bf16(aL, av[1], bv[0][0], bv[0][2]); mma_bf16(aH, av[1], bv[0][1], bv[0][3]);
                mma_bf16(aL, av[0], bv[2][0], bv[2][2]); mma_bf16(aH, av[0], bv[2][1], bv[2][3]);
                mma_bf16(aL, av[2], bv[0][0], bv[0][2]); mma_bf16(aH, av[2], bv[0][1], bv[0][3]);
                mma_bf16(aL, av[1], bv[1][0], bv[1][2]); mma_bf16(aH, av[1], bv[1][1], bv[1][3]);
            }
        }

        // score = c2 - 2*dot; running argmin (ascending n -> first-index ties)
        const float* c2s = (const float*)(smem + OFF_C2);
        #pragma unroll
        for (int nt = 0; nt < 8; nt++) {
            int n0 = c * CHN + nt * 8 + (lane & 3) * 2;
            float2 c2v = *(const float2*)(c2s + n0);
            float s;
            s = fmaf(-2.0f, acc[nt][0], c2v.x); if (s < mv[0]) { mv[0] = s; mi[0] = n0; }
            s = fmaf(-2.0f, acc[nt][1], c2v.y); if (s < mv[0]) { mv[0] = s; mi[0] = n0 + 1; }
            s = fmaf(-2.0f, acc[nt][2], c2v.x); if (s < mv[1]) { mv[1] = s; mi[1] = n0; }
            s = fmaf(-2.0f, acc[nt][3], c2v.y); if (s < mv[1]) { mv[1] = s; mi[1] = n0 + 1; }
        }
        __syncthreads();   // all warps done reading buf before chunk c+2 overwrites it
    }

    // ---- reduce argmin across the 4 lanes of each row-quad ----
    #pragma unroll
    for (int m = 1; m <= 2; m <<= 1) {
        #pragma unroll
        for (int q = 0; q < 2; q++) {
            float ov = __shfl_xor_sync(0xffffffffu, mv[q], m);
            int   oi = __shfl_xor_sync(0xffffffffu, mi[q], m);
            if (ov < mv[q] || (ov == mv[q] && oi < mi[q])) { mv[q] = ov; mi[q] = oi; }
        }
    }
    if ((lane & 3) == 0) {
        int r0 = m0 + (lane >> 2);          // rows r0 and r0+8
        ((int*)(smem + OFF_ASSIGN))[r0]     = mi[0];
        ((int*)(smem + OFF_ASSIGN))[r0 + 8] = mi[1];
        if (assign_out != nullptr) {
            long long gA = gp0 + r0, gB = gp0 + r0 + 8;
            if (gA < NPTS) assign_out[gA] = (float)mi[0];
            if (gB < NPTS) assign_out[gB] = (float)mi[1];
        }
    }
    __syncthreads();

    // ---- segment sums: re-read F row, vectorized global reductions ----
    {
        int pt = tid >> 1, half = tid & 1;
        long long gp = gp0 + pt;
        if (gp < NPTS) {
            int k = ((const int*)(smem + OFF_ASSIGN))[pt];
            float* dst = g_sums + (size_t)k * DIM;
            const float4* fr = (const float4*)(F + gp * DIM);
            #pragma unroll
            for (int i = 0; i < 16; i++) {
                int d0 = half * 64 + i * 4;
                float4 v = fr[d0 >> 2];
                asm volatile("red.global.add.v4.f32 [%0], {%1,%2,%3,%4};"
                             :: "l"(dst + d0), "f"(v.x), "f"(v.y), "f"(v.z), "f"(v.w) : "memory");
            }
            if (half == 0)
                asm volatile("red.global.add.f32 [%0], %1;"
                             :: "l"(g_counts + k), "f"(1.0f) : "memory");
        }
    }
}

// new_centers = sums / max(counts, 1)
__global__ void finalize_kernel(float* __restrict__ out) {
    int i = blockIdx.x * blockDim.x + threadIdx.x;
    if (i < KC * DIM) {
        int k = i >> 7;
        out[i] = g_sums[i] / fmaxf(g_counts[k], 1.0f);
    }
}

extern "C" void kernel_launch(void* const* d_in, const int* in_sizes, int n_in,
                              void* d_out, int out_size) {
    const float* F       = (const float*)d_in[0];
    const float* centers = (const float*)d_in[1];
    float* out = (float*)d_out;
    float* assign_out = (out_size >= KC * DIM + NPTS) ? (out + KC * DIM) : nullptr;

    cudaFuncSetAttribute(assign_kernel, cudaFuncAttributeMaxDynamicSharedMemorySize,
                         SMEM_TOTAL);

    prep_kernel<<<64, 256>>>(centers);
    assign_kernel<<<(NPTS + BN - 1) / BN, 256, SMEM_TOTAL>>>(F, assign_out);
    finalize_kernel<<<(KC * DIM + 255) / 256, 256>>>(out);
}

// round 10
// speedup vs baseline: 3.3978x; 1.0121x over previous
#include <cuda_runtime.h>
#include <cuda_bf16.h>
#include <cstdint>

#define NPTS 200000
#define DIM  128
#define KC   512
#define BN   128
#define CHN  64
#define NCH  (KC / CHN)

// ---------------- device scratch (allocation-free rule) ----------------
__device__ float g_sums[KC * DIM];
__device__ float g_counts[KC];
__device__ float g_c2[KC];
__device__ __nv_bfloat16 g_bh[KC * DIM];
__device__ __nv_bfloat16 g_bm[KC * DIM];
__device__ __nv_bfloat16 g_bl[KC * DIM];

// ---------------- SMEM layout ----------------
// Rows padded to 272B: 8 consecutive rows hit 16B-units at banks 4i..4i+3
// (272/4 = 68 = 4 mod 32) -> conflict-free ldmatrix, no swizzle needed.
#define RS    272
#define A_SPL (128 * RS)          // 34816 per split
#define B_SPL (64 * RS)           // 17408 per split
#define B_BUF (3 * B_SPL)         // 52224 per buffer
#define OFF_ASSIGN 0              // 128 ints
#define OFF_C2     1024           // 512 floats
#define OFF_A      4096
#define OFF_B      (OFF_A + 3 * A_SPL)     // 108544
#define SMEM_TOTAL (OFF_B + 2 * B_BUF)     // 212992

__device__ __forceinline__ uint32_t smem_u32(const void* p) {
    uint32_t a;
    asm("{ .reg .u64 t; cvta.to.shared.u64 t, %1; cvt.u32.u64 %0, t; }" : "=r"(a) : "l"(p));
    return a;
}
__device__ __forceinline__ void ldsm4(uint32_t* r, uint32_t addr) {
    asm volatile("ldmatrix.sync.aligned.m8n8.x4.shared.b16 {%0,%1,%2,%3}, [%4];"
                 : "=r"(r[0]), "=r"(r[1]), "=r"(r[2]), "=r"(r[3]) : "r"(addr));
}
__device__ __forceinline__ void mma_bf16(float* c, const uint32_t* a, uint32_t b0, uint32_t b1) {
    asm volatile(
        "mma.sync.aligned.m16n8k16.row.col.f32.bf16.bf16.f32 "
        "{%0,%1,%2,%3}, {%4,%5,%6,%7}, {%8,%9}, {%0,%1,%2,%3};"
        : "+f"(c[0]), "+f"(c[1]), "+f"(c[2]), "+f"(c[3])
        : "r"(a[0]), "r"(a[1]), "r"(a[2]), "r"(a[3]), "r"(b0), "r"(b1));
}
__device__ __forceinline__ void cp_async16(uint32_t dst, const void* src) {
    uint64_t g;
    asm("cvta.to.global.u64 %0, %1;" : "=l"(g) : "l"(src));
    asm volatile("cp.async.cg.shared.global [%0], [%1], 16;" :: "r"(dst), "l"(g) : "memory");
}
#define CP_COMMIT() asm volatile("cp.async.commit_group;" ::: "memory")
#define CP_WAIT1()  asm volatile("cp.async.wait_group 1;" ::: "memory")
#define CP_WAIT0()  asm volatile("cp.async.wait_group 0;" ::: "memory")

__device__ __forceinline__ uint32_t pack2(__nv_bfloat16 a, __nv_bfloat16 b) {
    return (uint32_t)__bfloat16_as_ushort(a) | ((uint32_t)__bfloat16_as_ushort(b) << 16);
}

// ---------------- prep: zero scratch, c2, 3-way bf16 split of centers ----------------
__global__ void prep_kernel(const float* __restrict__ centers) {
    const int tid = threadIdx.x;
    const int t = blockIdx.x * 256 + tid;          // 0..16383
    *(float4*)(g_sums + t * 4) = make_float4(0.f, 0.f, 0.f, 0.f);
    if (t < KC) g_counts[t] = 0.0f;
    float4 v4 = *(const float4*)(centers + t * 4);
    float vv[4] = {v4.x, v4.y, v4.z, v4.w};
    #pragma unroll
    for (int e = 0; e < 4; e++) {
        float v = vv[e];
        __nv_bfloat16 h = __float2bfloat16(v);
        float r1 = v - __bfloat162float(h);
        __nv_bfloat16 m = __float2bfloat16(r1);
        float r2 = r1 - __bfloat162float(m);
        __nv_bfloat16 l = __float2bfloat16(r2);
        g_bh[t * 4 + e] = h;
        g_bm[t * 4 + e] = m;
        g_bl[t * 4 + e] = l;
    }
    int c = blockIdx.x * 8 + (tid >> 5);
    int lane = tid & 31;
    float4 cv = ((const float4*)(centers + (size_t)c * DIM))[lane];
    float s = cv.x * cv.x + cv.y * cv.y + cv.z * cv.z + cv.w * cv.w;
    #pragma unroll
    for (int mth = 16; mth > 0; mth >>= 1) s += __shfl_xor_sync(0xffffffffu, s, mth);
    if (lane == 0) g_c2[c] = s;
}

// ---------------- B chunk loader: 3 splits x 64 rows via cp.async ----------------
__device__ __forceinline__ void load_chunk(char* smem, uint32_t sb, int chunk, int buf, int tid) {
    const __nv_bfloat16* gsrc[3] = {g_bh, g_bm, g_bl};
    #pragma unroll
    for (int i = 0; i < 12; i++) {
        int u = i * 256 + tid;            // 0..3071
        int split = u >> 10;
        int r = (u >> 4) & 63;
        int q = u & 15;
        const __nv_bfloat16* src = gsrc[split] + ((size_t)(chunk * CHN + r)) * DIM + q * 8;
        uint32_t dst = sb + OFF_B + buf * B_BUF + split * B_SPL + r * RS + q * 16;
        cp_async16(dst, src);
    }
}

// ---------------- main fused kernel ----------------
__global__ __launch_bounds__(256, 1)
void assign_kernel(const float* __restrict__ F, float* __restrict__ assign_out) {
    extern __shared__ char smem[];
    const uint32_t sb = smem_u32(smem);
    const int tid  = threadIdx.x;
    const int wid  = tid >> 5;
    const int lane = tid & 31;
    const long long gp0 = (long long)blockIdx.x * BN;

    // c2 -> smem
    for (int i = tid; i < KC; i += 256) ((float*)(smem + OFF_C2))[i] = g_c2[i];

    // ---- Load + split A (F tile 128x128) ----
    {
        int row = tid >> 1, half = tid & 1;
        long long gp = gp0 + row;
        const float4* fr = (const float4*)(F + gp * DIM) + half * 16;
        #pragma unroll
        for (int g = 0; g < 8; g++) {
            float4 a = make_float4(0.f, 0.f, 0.f, 0.f), b = a;
            if (gp < NPTS) { a = fr[g * 2]; b = fr[g * 2 + 1]; }
            float v[8] = {a.x, a.y, a.z, a.w, b.x, b.y, b.z, b.w};
            __nv_bfloat16 h[8], m[8], l[8];
            #pragma unroll
            for (int e = 0; e < 8; e++) {
                h[e] = __float2bfloat16(v[e]);
                float r1 = v[e] - __bfloat162float(h[e]);
                m[e] = __float2bfloat16(r1);
                float r2 = r1 - __bfloat162float(m[e]);
                l[e] = __float2bfloat16(r2);
            }
            uint32_t doff = OFF_A + row * RS + (half * 64 + g * 8) * 2;
            *(uint4*)(smem + doff)             = make_uint4(pack2(h[0],h[1]), pack2(h[2],h[3]), pack2(h[4],h[5]), pack2(h[6],h[7]));
            *(uint4*)(smem + doff + A_SPL)     = make_uint4(pack2(m[0],m[1]), pack2(m[2],m[3]), pack2(m[4],m[5]), pack2(m[6],m[7]));
            *(uint4*)(smem + doff + 2 * A_SPL) = make_uint4(pack2(l[0],l[1]), pack2(l[2],l[3]), pack2(l[4],l[5]), pack2(l[6],l[7]));
        }
    }

    // prefetch chunk 0
    load_chunk(smem, sb, 0, 0, tid);
    CP_COMMIT();

    // per-lane fragment offsets (ldmatrix lane-address pattern)
    const int m0 = wid * 16;
    const int frow = (lane & 7) + ((lane >> 3) & 1) * 8;
    const int kblk = (lane >> 4) * 8;
    const uint32_t aoff = sb + OFF_A + (uint32_t)((m0 + frow) * RS + kblk * 2);
    const uint32_t boff = sb + OFF_B + (uint32_t)(frow * RS + kblk * 2);

    float mv[2] = {3.4e38f, 3.4e38f};
    int   mi[2] = {0, 0};

    #pragma unroll 1
    for (int c = 0; c < NCH; c++) {
        const int buf = c & 1;
        if (c + 1 < NCH) { load_chunk(smem, sb, c + 1, buf ^ 1, tid); CP_COMMIT(); CP_WAIT1(); }
        else             { CP_WAIT0(); }
        __syncthreads();

        float acc[8][4];
        #pragma unroll
        for (int nt = 0; nt < 8; nt++)
            #pragma unroll
            for (int r = 0; r < 4; r++) acc[nt][r] = 0.0f;

        const uint32_t bb = boff + buf * B_BUF;
        #pragma unroll
        for (int ks = 0; ks < 8; ks++) {
            uint32_t av[3][4];
            #pragma unroll
            for (int s = 0; s < 3; s++) ldsm4(av[s], aoff + s * A_SPL + ks * 32);
            // Load ALL B fragments for this k-step up front (12 ldsm, 48 regs)
            uint32_t bv[3][4][4];
            #pragma unroll
            for (int ntp = 0; ntp < 4; ntp++)
                #pragma unroll
                for (int s = 0; s < 3; s++)
                    ldsm4(bv[s][ntp], bb + s * B_SPL + ntp * (16 * RS) + ks * 32);
            // Product-major issue: 8 independent accumulators between reuse
            // products: hh, hm, mh, hl, lh, mm
            const int ap[6] = {0, 0, 1, 0, 2, 1};
            const int bp[6] = {0, 1, 0, 2, 0, 1};
            #pragma unroll
            for (int p = 0; p < 6; p++) {
                const uint32_t* a = av[ap[p]];
                #pragma unroll
                for (int ntp = 0; ntp < 4; ntp++) {
                    const uint32_t* b = bv[bp[p]][ntp];
                    mma_bf16(acc[2 * ntp],     a, b[0], b[2]);
                    mma_bf16(acc[2 * ntp + 1], a, b[1], b[3]);
                }
            }
        }

        // score = c2 - 2*dot; running argmin (ascending n -> first-index ties)
        const float* c2s = (const float*)(smem + OFF_C2);
        #pragma unroll
        for (int nt = 0; nt < 8; nt++) {
            int n0 = c * CHN + nt * 8 + (lane & 3) * 2;
            float2 c2v = *(const float2*)(c2s + n0);
            float s;
            s = fmaf(-2.0f, acc[nt][0], c2v.x); if (s < mv[0]) { mv[0] = s; mi[0] = n0; }
            s = fmaf(-2.0f, acc[nt][1], c2v.y); if (s < mv[0]) { mv[0] = s; mi[0] = n0 + 1; }
            s = fmaf(-2.0f, acc[nt][2], c2v.x); if (s < mv[1]) { mv[1] = s; mi[1] = n0; }
            s = fmaf(-2.0f, acc[nt][3], c2v.y); if (s < mv[1]) { mv[1] = s; mi[1] = n0 + 1; }
        }
        __syncthreads();   // all warps done reading buf before it is overwritten
    }

    // ---- reduce argmin across the 4 lanes of each row-quad ----
    #pragma unroll
    for (int m = 1; m <= 2; m <<= 1) {
        #pragma unroll
        for (int q = 0; q < 2; q++) {
            float ov = __shfl_xor_sync(0xffffffffu, mv[q], m);
            int   oi = __shfl_xor_sync(0xffffffffu, mi[q], m);
            if (ov < mv[q] || (ov == mv[q] && oi < mi[q])) { mv[q] = ov; mi[q] = oi; }
        }
    }
    if ((lane & 3) == 0) {
        int r0 = m0 + (lane >> 2);          // rows r0 and r0+8
        ((int*)(smem + OFF_ASSIGN))[r0]     = mi[0];
        ((int*)(smem + OFF_ASSIGN))[r0 + 8] = mi[1];
        if (assign_out != nullptr) {
            long long gA = gp0 + r0, gB = gp0 + r0 + 8;
            if (gA < NPTS) assign_out[gA] = (float)mi[0];
            if (gB < NPTS) assign_out[gB] = (float)mi[1];
        }
    }
    __syncthreads();

    // ---- segment sums: re-read F row, vectorized global reductions ----
    {
        int pt = tid >> 1, half = tid & 1;
        long long gp = gp0 + pt;
        if (gp < NPTS) {
            int k = ((const int*)(smem + OFF_ASSIGN))[pt];
            float* dst = g_sums + (size_t)k * DIM;
            const float4* fr = (const float4*)(F + gp * DIM);
            #pragma unroll
            for (int i = 0; i < 16; i++) {
                int d0 = half * 64 + i * 4;
                float4 v = fr[d0 >> 2];
                asm volatile("red.global.add.v4.f32 [%0], {%1,%2,%3,%4};"
                             :: "l"(dst + d0), "f"(v.x), "f"(v.y), "f"(v.z), "f"(v.w) : "memory");
            }
            if (half == 0)
                asm volatile("red.global.add.f32 [%0], %1;"
                             :: "l"(g_counts + k), "f"(1.0f) : "memory");
        }
    }
}

// new_centers = sums / max(counts, 1)
__global__ void finalize_kernel(float* __restrict__ out) {
    int i = blockIdx.x * blockDim.x + threadIdx.x;
    if (i < KC * DIM) {
        int k = i >> 7;
        out[i] = g_sums[i] / fmaxf(g_counts[k], 1.0f);
    }
}

extern "C" void kernel_launch(void* const* d_in, const int* in_sizes, int n_in,
                              void* d_out, int out_size) {
    const float* F       = (const float*)d_in[0];
    const float* centers = (const float*)d_in[1];
    float* out = (float*)d_out;
    float* assign_out = (out_size >= KC * DIM + NPTS) ? (out + KC * DIM) : nullptr;

    cudaFuncSetAttribute(assign_kernel, cudaFuncAttributeMaxDynamicSharedMemorySize,
                         SMEM_TOTAL);

    prep_kernel<<<64, 256>>>(centers);
    assign_kernel<<<(NPTS + BN - 1) / BN, 256, SMEM_TOTAL>>>(F, assign_out);
    finalize_kernel<<<(KC * DIM + 255) / 256, 256>>>(out);
}

// round 16
// speedup vs baseline: 5.5558x; 1.6351x over previous
#include <cuda_runtime.h>
#include <cuda_fp16.h>
#include <cstdint>

#define NPTS 200000
#define DIM  128
#define KC   512
#define BN   128
#define CHN  64
#define NCH  (KC / CHN)

// ---------------- device scratch (allocation-free rule) ----------------
__device__ float g_sums[KC * DIM];
__device__ float g_counts[KC];
__device__ float g_c2[KC];
__device__ __half g_bh[KC * DIM];   // fp16 high part of centers
__device__ __half g_bm[KC * DIM];   // fp16 residual part

// ---------------- SMEM layout ----------------
// Rows padded to 272B: 8 consecutive rows hit 16B-units at banks 4i..4i+3
// (272/4 = 68 = 4 mod 32) -> conflict-free ldmatrix, no swizzle needed.
#define RS    272
#define A_SPL (128 * RS)          // 34816 per split
#define B_SPL (64 * RS)           // 17408 per split
#define B_BUF (2 * B_SPL)         // 34816 per buffer (2 splits)
#define OFF_ASSIGN 0              // 128 ints
#define OFF_C2     1024           // 512 floats
#define OFF_A      4096
#define OFF_B      (OFF_A + 2 * A_SPL)     // 73728
#define SMEM_TOTAL (OFF_B + 2 * B_BUF)     // 143360

__device__ __forceinline__ uint32_t smem_u32(const void* p) {
    uint32_t a;
    asm("{ .reg .u64 t; cvta.to.shared.u64 t, %1; cvt.u32.u64 %0, t; }" : "=r"(a) : "l"(p));
    return a;
}
__device__ __forceinline__ void ldsm4(uint32_t* r, uint32_t addr) {
    asm volatile("ldmatrix.sync.aligned.m8n8.x4.shared.b16 {%0,%1,%2,%3}, [%4];"
                 : "=r"(r[0]), "=r"(r[1]), "=r"(r[2]), "=r"(r[3]) : "r"(addr));
}
__device__ __forceinline__ void mma_f16(float* c, const uint32_t* a, uint32_t b0, uint32_t b1) {
    asm volatile(
        "mma.sync.aligned.m16n8k16.row.col.f32.f16.f16.f32 "
        "{%0,%1,%2,%3}, {%4,%5,%6,%7}, {%8,%9}, {%0,%1,%2,%3};"
        : "+f"(c[0]), "+f"(c[1]), "+f"(c[2]), "+f"(c[3])
        : "r"(a[0]), "r"(a[1]), "r"(a[2]), "r"(a[3]), "r"(b0), "r"(b1));
}
__device__ __forceinline__ void cp_async16(uint32_t dst, const void* src) {
    uint64_t g;
    asm("cvta.to.global.u64 %0, %1;" : "=l"(g) : "l"(src));
    asm volatile("cp.async.cg.shared.global [%0], [%1], 16;" :: "r"(dst), "l"(g) : "memory");
}
#define CP_COMMIT() asm volatile("cp.async.commit_group;" ::: "memory")
#define CP_WAIT1()  asm volatile("cp.async.wait_group 1;" ::: "memory")
#define CP_WAIT0()  asm volatile("cp.async.wait_group 0;" ::: "memory")

__device__ __forceinline__ uint32_t pack2h(__half a, __half b) {
    return (uint32_t)__half_as_ushort(a) | ((uint32_t)__half_as_ushort(b) << 16);
}

// ---------------- prep: zero scratch, c2, 2-way fp16 split of centers ----------------
__global__ void prep_kernel(const float* __restrict__ centers) {
    const int tid = threadIdx.x;
    const int t = blockIdx.x * 256 + tid;          // 0..16383
    *(float4*)(g_sums + t * 4) = make_float4(0.f, 0.f, 0.f, 0.f);
    if (t < KC) g_counts[t] = 0.0f;
    float4 v4 = *(const float4*)(centers + t * 4);
    float vv[4] = {v4.x, v4.y, v4.z, v4.w};
    #pragma unroll
    for (int e = 0; e < 4; e++) {
        float v = vv[e];
        __half h = __float2half_rn(v);
        float r1 = v - __half2float(h);
        __half m = __float2half_rn(r1);
        g_bh[t * 4 + e] = h;
        g_bm[t * 4 + e] = m;
    }
    int c = blockIdx.x * 8 + (tid >> 5);
    int lane = tid & 31;
    float4 cv = ((const float4*)(centers + (size_t)c * DIM))[lane];
    float s = cv.x * cv.x + cv.y * cv.y + cv.z * cv.z + cv.w * cv.w;
    #pragma unroll
    for (int mth = 16; mth > 0; mth >>= 1) s += __shfl_xor_sync(0xffffffffu, s, mth);
    if (lane == 0) g_c2[c] = s;
}

// ---------------- B chunk loader: 2 splits x 64 rows via cp.async ----------------
__device__ __forceinline__ void load_chunk(char* smem, uint32_t sb, int chunk, int buf, int tid) {
    const __half* gsrc[2] = {g_bh, g_bm};
    #pragma unroll
    for (int i = 0; i < 8; i++) {
        int u = i * 256 + tid;            // 0..2047
        int split = u >> 10;
        int r = (u >> 4) & 63;
        int q = u & 15;
        const __half* src = gsrc[split] + ((size_t)(chunk * CHN + r)) * DIM + q * 8;
        uint32_t dst = sb + OFF_B + buf * B_BUF + split * B_SPL + r * RS + q * 16;
        cp_async16(dst, src);
    }
}

// ---------------- main fused kernel ----------------
__global__ __launch_bounds__(256, 1)
void assign_kernel(const float* __restrict__ F, float* __restrict__ assign_out) {
    extern __shared__ char smem[];
    const uint32_t sb = smem_u32(smem);
    const int tid  = threadIdx.x;
    const int wid  = tid >> 5;
    const int lane = tid & 31;
    const long long gp0 = (long long)blockIdx.x * BN;

    // c2 -> smem
    for (int i = tid; i < KC; i += 256) ((float*)(smem + OFF_C2))[i] = g_c2[i];

    // ---- Load + split A (F tile 128x128) ----
    {
        int row = tid >> 1, half = tid & 1;
        long long gp = gp0 + row;
        const float4* fr = (const float4*)(F + gp * DIM) + half * 16;
        #pragma unroll
        for (int g = 0; g < 8; g++) {
            float4 a = make_float4(0.f, 0.f, 0.f, 0.f), b = a;
            if (gp < NPTS) { a = fr[g * 2]; b = fr[g * 2 + 1]; }
            float v[8] = {a.x, a.y, a.z, a.w, b.x, b.y, b.z, b.w};
            __half h[8], m[8];
            #pragma unroll
            for (int e = 0; e < 8; e++) {
                h[e] = __float2half_rn(v[e]);
                float r1 = v[e] - __half2float(h[e]);
                m[e] = __float2half_rn(r1);
            }
            uint32_t doff = OFF_A + row * RS + (half * 64 + g * 8) * 2;
            *(uint4*)(smem + doff)         = make_uint4(pack2h(h[0],h[1]), pack2h(h[2],h[3]), pack2h(h[4],h[5]), pack2h(h[6],h[7]));
            *(uint4*)(smem + doff + A_SPL) = make_uint4(pack2h(m[0],m[1]), pack2h(m[2],m[3]), pack2h(m[4],m[5]), pack2h(m[6],m[7]));
        }
    }

    // prefetch chunk 0
    load_chunk(smem, sb, 0, 0, tid);
    CP_COMMIT();

    // per-lane fragment offsets (ldmatrix lane-address pattern)
    const int m0 = wid * 16;
    const int frow = (lane & 7) + ((lane >> 3) & 1) * 8;
    const int kblk = (lane >> 4) * 8;
    const uint32_t aoff = sb + OFF_A + (uint32_t)((m0 + frow) * RS + kblk * 2);
    const uint32_t boff = sb + OFF_B + (uint32_t)(frow * RS + kblk * 2);

    float mv[2] = {3.4e38f, 3.4e38f};
    int   mi[2] = {0, 0};

    #pragma unroll 1
    for (int c = 0; c < NCH; c++) {
        const int buf = c & 1;
        if (c + 1 < NCH) { load_chunk(smem, sb, c + 1, buf ^ 1, tid); CP_COMMIT(); CP_WAIT1(); }
        else             { CP_WAIT0(); }
        __syncthreads();

        float acc[8][4];
        #pragma unroll
        for (int nt = 0; nt < 8; nt++)
            #pragma unroll
            for (int r = 0; r < 4; r++) acc[nt][r] = 0.0f;

        const uint32_t bb = boff + buf * B_BUF;
        #pragma unroll
        for (int ks = 0; ks < 8; ks++) {
            uint32_t av[2][4];
            #pragma unroll
            for (int s = 0; s < 2; s++) ldsm4(av[s], aoff + s * A_SPL + ks * 32);
            uint32_t bv[2][4][4];
            #pragma unroll
            for (int ntp = 0; ntp < 4; ntp++)
                #pragma unroll
                for (int s = 0; s < 2; s++)
                    ldsm4(bv[s][ntp], bb + s * B_SPL + ntp * (16 * RS) + ks * 32);
            // products: hh, hm, mh  (mm ~2^-24, dropped)
            const int ap[3] = {0, 0, 1};
            const int bp[3] = {0, 1, 0};
            #pragma unroll
            for (int p = 0; p < 3; p++) {
                const uint32_t* a = av[ap[p]];
                #pragma unroll
                for (int ntp = 0; ntp < 4; ntp++) {
                    const uint32_t* b = bv[bp[p]][ntp];
                    mma_f16(acc[2 * ntp],     a, b[0], b[2]);
                    mma_f16(acc[2 * ntp + 1], a, b[1], b[3]);
                }
            }
        }

        // score = c2 - 2*dot; running argmin (ascending n -> first-index ties)
        const float* c2s = (const float*)(smem + OFF_C2);
        #pragma unroll
        for (int nt = 0; nt < 8; nt++) {
            int n0 = c * CHN + nt * 8 + (lane & 3) * 2;
            float2 c2v = *(const float2*)(c2s + n0);
            float s;
            s = fmaf(-2.0f, acc[nt][0], c2v.x); if (s < mv[0]) { mv[0] = s; mi[0] = n0; }
            s = fmaf(-2.0f, acc[nt][1], c2v.y); if (s < mv[0]) { mv[0] = s; mi[0] = n0 + 1; }
            s = fmaf(-2.0f, acc[nt][2], c2v.x); if (s < mv[1]) { mv[1] = s; mi[1] = n0; }
            s = fmaf(-2.0f, acc[nt][3], c2v.y); if (s < mv[1]) { mv[1] = s; mi[1] = n0 + 1; }
        }
        __syncthreads();   // all warps done reading buf before it is overwritten
    }

    // ---- reduce argmin across the 4 lanes of each row-quad ----
    #pragma unroll
    for (int m = 1; m <= 2; m <<= 1) {
        #pragma unroll
        for (int q = 0; q < 2; q++) {
            float ov = __shfl_xor_sync(0xffffffffu, mv[q], m);
            int   oi = __shfl_xor_sync(0xffffffffu, mi[q], m);
            if (ov < mv[q] || (ov == mv[q] && oi < mi[q])) { mv[q] = ov; mi[q] = oi; }
        }
    }
    if ((lane & 3) == 0) {
        int r0 = m0 + (lane >> 2);          // rows r0 and r0+8
        ((int*)(smem + OFF_ASSIGN))[r0]     = mi[0];
        ((int*)(smem + OFF_ASSIGN))[r0 + 8] = mi[1];
        if (assign_out != nullptr) {
            long long gA = gp0 + r0, gB = gp0 + r0 + 8;
            if (gA < NPTS) assign_out[gA] = (float)mi[0];
            if (gB < NPTS) assign_out[gB] = (float)mi[1];
        }
    }
    __syncthreads();

    // ---- segment sums: re-read F row, vectorized global reductions ----
    {
        int pt = tid >> 1, half = tid & 1;
        long long gp = gp0 + pt;
        if (gp < NPTS) {
            int k = ((const int*)(smem + OFF_ASSIGN))[pt];
            float* dst = g_sums + (size_t)k * DIM;
            const float4* fr = (const float4*)(F + gp * DIM);
            #pragma unroll
            for (int i = 0; i < 16; i++) {
                int d0 = half * 64 + i * 4;
                float4 v = fr[d0 >> 2];
                asm volatile("red.global.add.v4.f32 [%0], {%1,%2,%3,%4};"
                             :: "l"(dst + d0), "f"(v.x), "f"(v.y), "f"(v.z), "f"(v.w) : "memory");
            }
            if (half == 0)
                asm volatile("red.global.add.f32 [%0], %1;"
                             :: "l"(g_counts + k), "f"(1.0f) : "memory");
        }
    }
}

// new_centers = sums / max(counts, 1)
__global__ void finalize_kernel(float* __restrict__ out) {
    int i = blockIdx.x * blockDim.x + threadIdx.x;
    if (i < KC * DIM) {
        int k = i >> 7;
        out[i] = g_sums[i] / fmaxf(g_counts[k], 1.0f);
    }
}

extern "C" void kernel_launch(void* const* d_in, const int* in_sizes, int n_in,
                              void* d_out, int out_size) {
    const float* F       = (const float*)d_in[0];
    const float* centers = (const float*)d_in[1];
    float* out = (float*)d_out;
    float* assign_out = (out_size >= KC * DIM + NPTS) ? (out + KC * DIM) : nullptr;

    cudaFuncSetAttribute(assign_kernel, cudaFuncAttributeMaxDynamicSharedMemorySize,
                         SMEM_TOTAL);

    prep_kernel<<<64, 256>>>(centers);
    assign_kernel<<<(NPTS + BN - 1) / BN, 256, SMEM_TOTAL>>>(F, assign_out);
    finalize_kernel<<<(KC * DIM + 255) / 256, 256>>>(out);
}